// round 9
// baseline (speedup 1.0000x reference)
#include <cuda_runtime.h>
#include <cuda_bf16.h>
#include <cstdint>

// HyenaSE gated causal depthwise conv via banded-Toeplitz GEMM on
// mma.sync.m16n8k16 (bf16, base-ISA -> compiles for sm_103 target).
// y[b,d,l] = q * sum_s (k*x)[b,d,l-s] * h[d%256][127-s]
//
// Block = (group g, batch b). A[i][j] = h[g][j-i-1] for j in [i+1,i+128]
// (128x256 banded Toeplitz), bf16 hi+lo in smem, built once.
// Per channel (16/block): B[n][j] = kx[128n-128+j] (32x256) hi+lo,
// double-buffered. D[m][n] = y[128n+m], fp32 register fragments, 3-pass
// Markidis split. Warp w (m-rows 16w..16w+15) only touches k-chunks
// [w, w+8] (band). Rows padded to 528B (stride = 4 mod 32 words) ->
// conflict-free ldmatrix. Epilogue: D-frags -> padded smem transpose ->
// q-gated coalesced float4 stores. x,k (next ch) + q (cur ch) prefetched
// to registers before the MMA loop.

typedef unsigned long long u64;

#define B_  2
#define D_  4096
#define L_  4096
#define G_  256
#define HL_ 128

static constexpr int THREADS = 256;
static constexpr int NCH = 16;

static constexpr int APITCH_B = 528;          // bytes per A/B row (264 bf16)
static constexpr int EPI_PITCH = 132;         // floats per epi row

// smem byte offsets
static constexpr int SM_AH  = 0;              // 128*528 = 67584
static constexpr int SM_AL  = 67584;
static constexpr int SM_B   = 135168;         // 2 bufs x (Bh 16896 + Bl 16896)
static constexpr int BBUF   = 33792;
static constexpr int BLO    = 16896;
static constexpr int SM_EPI = SM_B + 2 * BBUF;          // 202752
static constexpr int SM_TOTAL = SM_EPI + 32 * EPI_PITCH * 4;  // 219648

__device__ __forceinline__ void ldsm4(uint32_t* r, uint32_t addr) {
    asm volatile("ldmatrix.sync.aligned.m8n8.x4.shared.b16 {%0,%1,%2,%3}, [%4];"
        : "=r"(r[0]), "=r"(r[1]), "=r"(r[2]), "=r"(r[3]) : "r"(addr));
}
__device__ __forceinline__ void ldsm2(uint32_t* r, uint32_t addr) {
    asm volatile("ldmatrix.sync.aligned.m8n8.x2.shared.b16 {%0,%1}, [%2];"
        : "=r"(r[0]), "=r"(r[1]) : "r"(addr));
}
__device__ __forceinline__ void mma16816(float* d, const uint32_t* a, const uint32_t* b) {
    asm volatile("mma.sync.aligned.m16n8k16.row.col.f32.bf16.bf16.f32 "
        "{%0,%1,%2,%3}, {%4,%5,%6,%7}, {%8,%9}, {%0,%1,%2,%3};"
        : "+f"(d[0]), "+f"(d[1]), "+f"(d[2]), "+f"(d[3])
        : "r"(a[0]), "r"(a[1]), "r"(a[2]), "r"(a[3]), "r"(b[0]), "r"(b[1]));
}

__device__ __forceinline__ uint32_t pack_hi(float a, float b, float& ra, float& rb) {
    __nv_bfloat16 ha = __float2bfloat16(a), hb = __float2bfloat16(b);
    ra = a - __bfloat162float(ha);
    rb = b - __bfloat162float(hb);
    return (uint32_t)__bfloat16_as_ushort(ha) | ((uint32_t)__bfloat16_as_ushort(hb) << 16);
}
__device__ __forceinline__ uint32_t pack_lo(float ra, float rb) {
    __nv_bfloat16 la = __float2bfloat16(ra), lb = __float2bfloat16(rb);
    return (uint32_t)__bfloat16_as_ushort(la) | ((uint32_t)__bfloat16_as_ushort(lb) << 16);
}

__global__ void __launch_bounds__(THREADS, 1)
hyena_mma_kernel(const float* __restrict__ x, const float* __restrict__ k,
                 const float* __restrict__ q, const float* __restrict__ h,
                 float* __restrict__ out)
{
    extern __shared__ __align__(16) char sm[];
    const uint32_t sbase = (uint32_t)__cvta_generic_to_shared(sm);
    const int tid = threadIdx.x, wid = tid >> 5, lid = tid & 31;
    const int g = blockIdx.x, b = blockIdx.y;

    // ---- Build A (once): A[m][j] = h[g][j-m-1], band j in [m+1, m+128]
    {
        const float* hg = h + g * HL_;
        const int m  = tid >> 1;
        const int jh = (tid & 1) * 128;
        #pragma unroll
        for (int cc = 0; cc < 16; cc++) {
            const int j0 = jh + cc * 8;
            uint32_t wh[4], wl[4];
            #pragma unroll
            for (int p = 0; p < 4; p++) {
                int ja = j0 + 2 * p;
                int sa = ja - m - 1, sb = sa + 1;
                float va = (sa >= 0 && sa < HL_) ? hg[sa] : 0.f;
                float vb = (sb >= 0 && sb < HL_) ? hg[sb] : 0.f;
                float ra, rb;
                wh[p] = pack_hi(va, vb, ra, rb);
                wl[p] = pack_lo(ra, rb);
            }
            const uint32_t off = (uint32_t)m * APITCH_B + (uint32_t)j0 * 2;
            *(uint4*)(sm + SM_AH + off) = make_uint4(wh[0], wh[1], wh[2], wh[3]);
            *(uint4*)(sm + SM_AL + off) = make_uint4(wl[0], wl[1], wl[2], wl[3]);
        }
    }

    // Per-thread B-build geometry: row n, 4-col groups at j = 4*(tid&7)+32c
    const int bn = tid >> 3;
    const int bj = 4 * (tid & 7);

    // Convert 4 kx values -> Bh/Bl rows of buffer nb
    auto cvtStore = [&](int nb, int c, float v0, float v1, float v2, float v3) {
        float r0, r1, r2, r3;
        uint32_t h01 = pack_hi(v0, v1, r0, r1);
        uint32_t h23 = pack_hi(v2, v3, r2, r3);
        uint32_t l01 = pack_lo(r0, r1);
        uint32_t l23 = pack_lo(r2, r3);
        const uint32_t off = (uint32_t)bn * APITCH_B + (uint32_t)(bj + 32 * c) * 2;
        char* bh = sm + SM_B + nb * BBUF;
        *(uint2*)(bh + off)       = make_uint2(h01, h23);
        *(uint2*)(bh + BLO + off) = make_uint2(l01, l23);
    };

    // ---- Prologue: build B[0] for channel 0 (direct LDG)
    {
        const long row = ((long)b * D_ + g) * L_;
        #pragma unroll
        for (int c = 0; c < 8; c++) {
            if (bn == 0 && c < 4) { cvtStore(0, c, 0.f, 0.f, 0.f, 0.f); continue; }
            const long pos = row + 128 * bn - 128 + bj + 32 * c;
            float4 xv = *(const float4*)(x + pos);
            float4 kv = *(const float4*)(k + pos);
            cvtStore(0, c, xv.x * kv.x, xv.y * kv.y, xv.z * kv.z, xv.w * kv.w);
        }
    }
    __syncthreads();

    // ldmatrix lane address bases
    const int amat = lid >> 3, arow = lid & 7;
    const uint32_t aoffL = (uint32_t)((16 * wid + (amat & 1) * 8 + arow) * APITCH_B
                                      + ((amat >> 1) * 8) * 2);
    const uint32_t aH = sbase + SM_AH + aoffL;
    const uint32_t boffL = (uint32_t)((lid & 7) * APITCH_B + ((lid >> 3) & 1) * 16);

    // Transpose-store geometry: thread covers l = 128*tn + 16*tm .. +15
    const int tn = tid >> 3, tm = 16 * (tid & 7);
    const int lt = 128 * tn + tm;
    float* epi = (float*)(sm + SM_EPI);

    #pragma unroll 1
    for (int ch = 0; ch < NCH; ch++) {
        const long rowc = ((long)b * D_ + g + 256 * ch) * L_;

        // -- step a: prefetch x,k (ch+1) and q (ch) into registers
        float4 xr[8], kr[8], qv[4];
        if (ch + 1 < NCH) {
            const long rown = rowc + 256L * L_;
            #pragma unroll
            for (int c = 0; c < 8; c++) {
                if (bn == 0 && c < 4) {
                    xr[c] = make_float4(0.f, 0.f, 0.f, 0.f);
                    kr[c] = make_float4(0.f, 0.f, 0.f, 0.f);
                } else {
                    const long pos = rown + 128 * bn - 128 + bj + 32 * c;
                    xr[c] = *(const float4*)(x + pos);
                    kr[c] = *(const float4*)(k + pos);
                }
            }
        }
        #pragma unroll
        for (int i = 0; i < 4; i++)
            qv[i] = *(const float4*)(q + rowc + lt + 4 * i);

        // -- step b: MMA mainloop on B[ch&1]
        float d[4][4];
        #pragma unroll
        for (int nc = 0; nc < 4; nc++)
            #pragma unroll
            for (int i = 0; i < 4; i++) d[nc][i] = 0.f;

        const uint32_t bbase = sbase + SM_B + (uint32_t)((ch & 1) * BBUF) + boffL;
        #pragma unroll 1
        for (int c = 0; c < 9; c++) {
            const uint32_t koff = 32u * (uint32_t)(wid + c);
            uint32_t ah[4], al[4];
            ldsm4(ah, aH + koff);
            ldsm4(al, aH + (uint32_t)(SM_AL - SM_AH) + koff);
            #pragma unroll
            for (int nc = 0; nc < 4; nc++) {
                const uint32_t baddr = bbase + (uint32_t)(nc * 8 * APITCH_B) + koff;
                uint32_t bh[2], bl[2];
                ldsm2(bh, baddr);
                ldsm2(bl, baddr + BLO);
                mma16816(d[nc], ah, bh);
                mma16816(d[nc], ah, bl);
                mma16816(d[nc], al, bh);
            }
        }

        // -- step c: D frags -> epi (conflict-free via 132-float pitch)
        {
            const int m = 16 * wid + (lid >> 2);
            #pragma unroll
            for (int nc = 0; nc < 4; nc++) {
                const int n = 8 * nc + 2 * (lid & 3);
                epi[n * EPI_PITCH + m]           = d[nc][0];
                epi[(n + 1) * EPI_PITCH + m]     = d[nc][1];
                epi[n * EPI_PITCH + m + 8]       = d[nc][2];
                epi[(n + 1) * EPI_PITCH + m + 8] = d[nc][3];
            }
        }
        __syncthreads();

        // -- step e: transpose read + q-gated store
        {
            float4* op = (float4*)(out + rowc + lt);
            const float4* ep = (const float4*)(epi + tn * EPI_PITCH + tm);
            #pragma unroll
            for (int i = 0; i < 4; i++) {
                float4 y = ep[i];
                op[i] = make_float4(qv[i].x * y.x, qv[i].y * y.y,
                                    qv[i].z * y.z, qv[i].w * y.w);
            }
        }

        // -- step f: convert prefetched x,k -> B[(ch+1)&1]
        if (ch + 1 < NCH) {
            const int nb = (ch + 1) & 1;
            #pragma unroll
            for (int c = 0; c < 8; c++)
                cvtStore(nb, c, xr[c].x * kr[c].x, xr[c].y * kr[c].y,
                                xr[c].z * kr[c].z, xr[c].w * kr[c].w);
        }
        __syncthreads();
    }
}

extern "C" void kernel_launch(void* const* d_in, const int* in_sizes, int n_in,
                              void* d_out, int out_size) {
    // metadata order: x, k, q, h  (all float32); output float32 (B,D,L)
    const float* x = (const float*)d_in[0];
    const float* k = (const float*)d_in[1];
    const float* q = (const float*)d_in[2];
    const float* h = (const float*)d_in[3];
    float* out = (float*)d_out;

    cudaFuncSetAttribute(hyena_mma_kernel,
                         cudaFuncAttributeMaxDynamicSharedMemorySize, SM_TOTAL);
    dim3 grid(G_, B_);   // 256 groups x 2 batches
    hyena_mma_kernel<<<grid, THREADS, SM_TOTAL>>>(x, k, q, h, out);
}

// round 11
// speedup vs baseline: 1.1355x; 1.1355x over previous
#include <cuda_runtime.h>
#include <cuda_bf16.h>
#include <cstdint>

// HyenaSE gated causal depthwise conv via banded-Toeplitz GEMM on
// mma.sync.m16n8k16 (bf16 base ISA; tcgen05 rejected at sm_103 target).
// y[b,d,l] = q * sum_s (k*x)[b,d,l-s] * h[d%256][127-s]
//
// R10: Toeplitz symmetry -> A tile content for (warp w, kstep w+c) is
// h[16c+s-r-1], independent of w. Whole A collapses to a 16x144 band
// array (hi+lo bf16, pitch 304B, conflict-free ldmatrix) = 10KB instead
// of 135KB. Smem 92KB -> 2 blocks/SM (occ 25%), regs forced <=128 by
// dropping register prefetches (cross-block overlap hides LDG latency).
// Per channel: B[n][j]=kx[128n-128+j] (32x256 hi+lo, double-buffered),
// D[m][n]=y[128n+m] fp32 frags, 3-pass Markidis split, 9 banded ksteps
// per warp. Epilogue: frag->padded smem transpose->q-gated float4 stores.

typedef unsigned long long u64;

#define B_  2
#define D_  4096
#define L_  4096
#define G_  256
#define HL_ 128

static constexpr int THREADS = 256;
static constexpr int NCH = 16;

static constexpr int APITCH = 304;            // Aband row pitch bytes (152 bf16)
static constexpr int BPITCH = 528;            // B row pitch bytes (264 bf16)
static constexpr int EPI_PITCH = 132;         // floats per epi row

// smem byte offsets
static constexpr int SM_ABH = 0;              // 16*304 = 4864
static constexpr int SM_ABL = 4864;
static constexpr int SM_B   = 9728;           // 2 bufs x (Bh 16896 + Bl 16896)
static constexpr int BLO    = 16896;
static constexpr int BBUF   = 33792;
static constexpr int SM_EPI = SM_B + 2 * BBUF;            // 77312
static constexpr int SM_TOTAL = SM_EPI + 32 * EPI_PITCH * 4;  // 94208

__device__ __forceinline__ void ldsm4(uint32_t* r, uint32_t addr) {
    asm volatile("ldmatrix.sync.aligned.m8n8.x4.shared.b16 {%0,%1,%2,%3}, [%4];"
        : "=r"(r[0]), "=r"(r[1]), "=r"(r[2]), "=r"(r[3]) : "r"(addr));
}
__device__ __forceinline__ void ldsm2(uint32_t* r, uint32_t addr) {
    asm volatile("ldmatrix.sync.aligned.m8n8.x2.shared.b16 {%0,%1}, [%2];"
        : "=r"(r[0]), "=r"(r[1]) : "r"(addr));
}
__device__ __forceinline__ void mma16816(float* d, const uint32_t* a, const uint32_t* b) {
    asm volatile("mma.sync.aligned.m16n8k16.row.col.f32.bf16.bf16.f32 "
        "{%0,%1,%2,%3}, {%4,%5,%6,%7}, {%8,%9}, {%0,%1,%2,%3};"
        : "+f"(d[0]), "+f"(d[1]), "+f"(d[2]), "+f"(d[3])
        : "r"(a[0]), "r"(a[1]), "r"(a[2]), "r"(a[3]), "r"(b[0]), "r"(b[1]));
}

__device__ __forceinline__ uint32_t pack_hi(float a, float b, float& ra, float& rb) {
    __nv_bfloat16 ha = __float2bfloat16(a), hb = __float2bfloat16(b);
    ra = a - __bfloat162float(ha);
    rb = b - __bfloat162float(hb);
    return (uint32_t)__bfloat16_as_ushort(ha) | ((uint32_t)__bfloat16_as_ushort(hb) << 16);
}
__device__ __forceinline__ uint32_t pack_lo(float ra, float rb) {
    __nv_bfloat16 la = __float2bfloat16(ra), lb = __float2bfloat16(rb);
    return (uint32_t)__bfloat16_as_ushort(la) | ((uint32_t)__bfloat16_as_ushort(lb) << 16);
}

__global__ void __launch_bounds__(THREADS, 2)
hyena_mma_kernel(const float* __restrict__ x, const float* __restrict__ k,
                 const float* __restrict__ q, const float* __restrict__ h,
                 float* __restrict__ out)
{
    extern __shared__ __align__(16) char sm[];
    const uint32_t sbase = (uint32_t)__cvta_generic_to_shared(sm);
    const int tid = threadIdx.x, wid = tid >> 5, lid = tid & 31;
    const int g = blockIdx.x, b = blockIdx.y;

    // ---- Build compact Toeplitz band: Aband[r][u] = h[g][u-r-1], u in [0,144)
    {
        const float* hg = h + g * HL_;
        const int r = tid & 15;
        const int u0 = (tid >> 4) * 9;        // 16 threads x 9 cols = 144
        __nv_bfloat16* abh = (__nv_bfloat16*)(sm + SM_ABH + r * APITCH);
        __nv_bfloat16* abl = (__nv_bfloat16*)(sm + SM_ABL + r * APITCH);
        #pragma unroll
        for (int i = 0; i < 9; i++) {
            const int u = u0 + i;
            const int s = u - r - 1;
            float v = (s >= 0 && s < HL_) ? hg[s] : 0.f;
            __nv_bfloat16 vh = __float2bfloat16(v);
            abh[u] = vh;
            abl[u] = __float2bfloat16(v - __bfloat162float(vh));
        }
    }

    // Per-thread B-build geometry: row bn, 4-col groups at j = bj + 32c
    const int bn = tid >> 3;
    const int bj = 4 * (tid & 7);

    auto cvtStore = [&](int nb, int c, float v0, float v1, float v2, float v3) {
        float r0, r1, r2, r3;
        uint32_t h01 = pack_hi(v0, v1, r0, r1);
        uint32_t h23 = pack_hi(v2, v3, r2, r3);
        uint32_t l01 = pack_lo(r0, r1);
        uint32_t l23 = pack_lo(r2, r3);
        const uint32_t off = (uint32_t)bn * BPITCH + (uint32_t)(bj + 32 * c) * 2;
        char* bh = sm + SM_B + nb * BBUF;
        *(uint2*)(bh + off)       = make_uint2(h01, h23);
        *(uint2*)(bh + BLO + off) = make_uint2(l01, l23);
    };
    auto buildB = [&](int nb, int ch) {
        const long row = ((long)b * D_ + g + 256 * ch) * L_;
        #pragma unroll
        for (int c = 0; c < 8; c++) {
            if (bn == 0 && c < 4) { cvtStore(nb, c, 0.f, 0.f, 0.f, 0.f); continue; }
            const long pos = row + 128 * bn - 128 + bj + 32 * c;
            float4 xv = *(const float4*)(x + pos);
            float4 kv = *(const float4*)(k + pos);
            cvtStore(nb, c, xv.x * kv.x, xv.y * kv.y, xv.z * kv.z, xv.w * kv.w);
        }
    };

    // ---- Prologue: build B[0] for channel 0
    buildB(0, 0);
    __syncthreads();

    // ldmatrix lane bases. A: warp-independent band array.
    const int amat = lid >> 3, arow = lid & 7;
    const uint32_t aH = sbase + SM_ABH
        + (uint32_t)(((amat & 1) * 8 + arow) * APITCH + ((amat >> 1) * 8) * 2);
    const uint32_t boffL = (uint32_t)((lid & 7) * BPITCH + ((lid >> 3) & 1) * 16);

    // Transpose-store geometry: thread covers l = 128*tn + tm .. +15
    const int tn = tid >> 3, tm = 16 * (tid & 7);
    const int lt = 128 * tn + tm;
    float* epi = (float*)(sm + SM_EPI);

    #pragma unroll 1
    for (int ch = 0; ch < NCH; ch++) {
        const long rowc = ((long)b * D_ + g + 256 * ch) * L_;

        // -- MMA mainloop on B[ch&1]; warp w covers ksteps w..w+8 (band)
        float d[4][4];
        #pragma unroll
        for (int nc = 0; nc < 4; nc++)
            #pragma unroll
            for (int i = 0; i < 4; i++) d[nc][i] = 0.f;

        const uint32_t bbase = sbase + SM_B + (uint32_t)((ch & 1) * BBUF) + boffL;
        #pragma unroll 1
        for (int c = 0; c < 9; c++) {
            uint32_t ah[4], al[4];
            ldsm4(ah, aH + (uint32_t)(32 * c));                       // Aband col 16c
            ldsm4(al, aH + (uint32_t)(SM_ABL - SM_ABH + 32 * c));
            const uint32_t koff = 32u * (uint32_t)(wid + c);          // B kstep w+c
            #pragma unroll
            for (int nc = 0; nc < 4; nc++) {
                const uint32_t baddr = bbase + (uint32_t)(nc * 8 * BPITCH) + koff;
                uint32_t bh[2], bl[2];
                ldsm2(bh, baddr);
                ldsm2(bl, baddr + BLO);
                mma16816(d[nc], ah, bh);
                mma16816(d[nc], ah, bl);
                mma16816(d[nc], al, bh);
            }
        }

        // -- D frags -> epi (bank-conflict-free via 132-float pitch)
        {
            const int m = 16 * wid + (lid >> 2);
            #pragma unroll
            for (int nc = 0; nc < 4; nc++) {
                const int n = 8 * nc + 2 * (lid & 3);
                epi[n * EPI_PITCH + m]           = d[nc][0];
                epi[(n + 1) * EPI_PITCH + m]     = d[nc][1];
                epi[n * EPI_PITCH + m + 8]       = d[nc][2];
                epi[(n + 1) * EPI_PITCH + m + 8] = d[nc][3];
            }
        }
        __syncthreads();

        // -- epilogue: q-gated coalesced stores
        {
            float4* op = (float4*)(out + rowc + lt);
            const float4* qp = (const float4*)(q + rowc + lt);
            const float4* ep = (const float4*)(epi + tn * EPI_PITCH + tm);
            #pragma unroll
            for (int i = 0; i < 4; i++) {
                float4 y = ep[i];
                float4 qv = qp[i];
                op[i] = make_float4(qv.x * y.x, qv.y * y.y, qv.z * y.z, qv.w * y.w);
            }
        }

        // -- build next channel's B (buffer was last read 2 iters ago)
        if (ch + 1 < NCH) buildB((ch + 1) & 1, ch + 1);
        __syncthreads();
    }
}

extern "C" void kernel_launch(void* const* d_in, const int* in_sizes, int n_in,
                              void* d_out, int out_size) {
    // metadata order: x, k, q, h  (all float32); output float32 (B,D,L)
    const float* x = (const float*)d_in[0];
    const float* k = (const float*)d_in[1];
    const float* q = (const float*)d_in[2];
    const float* h = (const float*)d_in[3];
    float* out = (float*)d_out;

    cudaFuncSetAttribute(hyena_mma_kernel,
                         cudaFuncAttributeMaxDynamicSharedMemorySize, SM_TOTAL);
    dim3 grid(G_, B_);   // 256 groups x 2 batches
    hyena_mma_kernel<<<grid, THREADS, SM_TOTAL>>>(x, k, q, h, out);
}

// round 12
// speedup vs baseline: 1.5117x; 1.3314x over previous
#include <cuda_runtime.h>
#include <cuda_bf16.h>
#include <cstdint>

// HyenaSE gated causal depthwise conv via banded-Toeplitz GEMM on
// mma.sync.m16n8k16 (bf16 base ISA; tcgen05 unsupported at sm_103 target).
// y[b,d,l] = q * sum_s (k*x)[b,d,l-s] * h[d%256][127-s]
//
// R12: R11 was latency-exposed (issue 17%, dur == traffic/achieved-BW):
// every x,k byte was a synchronous LDG on the critical path. Now raw x,k
// rows are staged into smem via cp.async.cg DURING the previous channel's
// MMA+epilogue; buildB converts from smem. q prefetched to regs before the
// MMA loop. 4 channels/block (grid 2048) smooths waves. Smem 91KB ->
// 2 blocks/SM.
// Core unchanged: 16x144 Toeplitz band array (hi+lo bf16) shared by all
// warps; B[n][j]=kx[128n-128+j] (32x256 hi+lo); D[m][n]=y[128n+m] fp32
// frags; 3-pass Markidis split; 9 banded ksteps/warp; epi via padded smem
// transpose -> q-gated float4 stores.

typedef unsigned long long u64;

#define B_  2
#define D_  4096
#define L_  4096
#define G_  256
#define HL_ 128

static constexpr int THREADS = 256;
static constexpr int NCHB = 4;                // channels per block

static constexpr int APITCH = 304;            // Aband row pitch bytes
static constexpr int BPITCH = 528;            // B row pitch bytes
static constexpr int EPI_PITCH = 132;         // floats per epi row

// smem byte offsets
static constexpr int SM_ABH   = 0;            // 16*304 = 4864
static constexpr int SM_ABL   = 4864;         // end 9728
static constexpr int SM_STG_X = 9728;         // 4096 floats = 16384
static constexpr int SM_STG_K = 26112;        // end 42496
static constexpr int SM_B     = 42496;        // Bh 16896 + Bl 16896
static constexpr int BLO      = 16896;
static constexpr int SM_EPI   = 76288;        // 32*132*4 = 16896
static constexpr int SM_TOTAL = 93184;        // 91 KB -> 2 blocks/SM

__device__ __forceinline__ void ldsm4(uint32_t* r, uint32_t addr) {
    asm volatile("ldmatrix.sync.aligned.m8n8.x4.shared.b16 {%0,%1,%2,%3}, [%4];"
        : "=r"(r[0]), "=r"(r[1]), "=r"(r[2]), "=r"(r[3]) : "r"(addr));
}
__device__ __forceinline__ void ldsm2(uint32_t* r, uint32_t addr) {
    asm volatile("ldmatrix.sync.aligned.m8n8.x2.shared.b16 {%0,%1}, [%2];"
        : "=r"(r[0]), "=r"(r[1]) : "r"(addr));
}
__device__ __forceinline__ void mma16816(float* d, const uint32_t* a, const uint32_t* b) {
    asm volatile("mma.sync.aligned.m16n8k16.row.col.f32.bf16.bf16.f32 "
        "{%0,%1,%2,%3}, {%4,%5,%6,%7}, {%8,%9}, {%0,%1,%2,%3};"
        : "+f"(d[0]), "+f"(d[1]), "+f"(d[2]), "+f"(d[3])
        : "r"(a[0]), "r"(a[1]), "r"(a[2]), "r"(a[3]), "r"(b[0]), "r"(b[1]));
}
__device__ __forceinline__ void cp16(uint32_t daddr, const void* g) {
    asm volatile("cp.async.cg.shared.global [%0], [%1], 16;"
                 :: "r"(daddr), "l"(g));
}

__device__ __forceinline__ uint32_t pack_hi(float a, float b, float& ra, float& rb) {
    __nv_bfloat16 ha = __float2bfloat16(a), hb = __float2bfloat16(b);
    ra = a - __bfloat162float(ha);
    rb = b - __bfloat162float(hb);
    return (uint32_t)__bfloat16_as_ushort(ha) | ((uint32_t)__bfloat16_as_ushort(hb) << 16);
}
__device__ __forceinline__ uint32_t pack_lo(float ra, float rb) {
    __nv_bfloat16 la = __float2bfloat16(ra), lb = __float2bfloat16(rb);
    return (uint32_t)__bfloat16_as_ushort(la) | ((uint32_t)__bfloat16_as_ushort(lb) << 16);
}

__global__ void __launch_bounds__(THREADS, 2)
hyena_mma_kernel(const float* __restrict__ x, const float* __restrict__ k,
                 const float* __restrict__ q, const float* __restrict__ h,
                 float* __restrict__ out)
{
    extern __shared__ __align__(16) char sm[];
    const uint32_t sbase = (uint32_t)__cvta_generic_to_shared(sm);
    const int tid = threadIdx.x, wid = tid >> 5, lid = tid & 31;
    const int g = blockIdx.x;
    const int b = blockIdx.y >> 2;
    const int chunk = blockIdx.y & 3;          // channel block: ch = 4*chunk + i

    // ---- Toeplitz band: Aband[r][u] = h[g][u-r-1], u in [0,144), hi+lo
    {
        const float* hg = h + g * HL_;
        const int r = tid & 15;
        const int u0 = (tid >> 4) * 9;
        __nv_bfloat16* abh = (__nv_bfloat16*)(sm + SM_ABH + r * APITCH);
        __nv_bfloat16* abl = (__nv_bfloat16*)(sm + SM_ABL + r * APITCH);
        #pragma unroll
        for (int i = 0; i < 9; i++) {
            const int u = u0 + i;
            const int s = u - r - 1;
            float v = (s >= 0 && s < HL_) ? hg[s] : 0.f;
            __nv_bfloat16 vh = __float2bfloat16(v);
            abh[u] = vh;
            abl[u] = __float2bfloat16(v - __bfloat162float(vh));
        }
    }

    // cp.async stage: raw x,k row of channel ch into smem staging
    auto stage = [&](int ch) {
        const long row = ((long)b * D_ + g + 256 * (4 * chunk + ch)) * L_;
        const float* xr = x + row;
        const float* kr = k + row;
        #pragma unroll
        for (int it = 0; it < 4; it++) {
            const uint32_t v = (uint32_t)(it * THREADS + tid);   // float4 idx
            cp16(sbase + SM_STG_X + v * 16, xr + 4 * v);
            cp16(sbase + SM_STG_K + v * 16, kr + 4 * v);
        }
        asm volatile("cp.async.commit_group;");
    };

    // B build from staged smem: B[n][j] = kx[128n-128+j], hi+lo
    const int bn = tid >> 3;
    const int bj = 4 * (tid & 7);
    auto buildB = [&]() {
        const float* xs = (const float*)(sm + SM_STG_X);
        const float* ks = (const float*)(sm + SM_STG_K);
        #pragma unroll
        for (int c = 0; c < 8; c++) {
            float v0 = 0.f, v1 = 0.f, v2 = 0.f, v3 = 0.f;
            if (!(bn == 0 && c < 4)) {
                const int pos = 128 * bn - 128 + bj + 32 * c;
                float4 xv = *(const float4*)(xs + pos);
                float4 kv = *(const float4*)(ks + pos);
                v0 = xv.x * kv.x; v1 = xv.y * kv.y;
                v2 = xv.z * kv.z; v3 = xv.w * kv.w;
            }
            float r0, r1, r2, r3;
            uint32_t h01 = pack_hi(v0, v1, r0, r1);
            uint32_t h23 = pack_hi(v2, v3, r2, r3);
            uint32_t l01 = pack_lo(r0, r1);
            uint32_t l23 = pack_lo(r2, r3);
            const uint32_t off = (uint32_t)bn * BPITCH + (uint32_t)(bj + 32 * c) * 2;
            *(uint2*)(sm + SM_B + off)       = make_uint2(h01, h23);
            *(uint2*)(sm + SM_B + BLO + off) = make_uint2(l01, l23);
        }
    };

    // ---- prologue: stage ch0, build it, kick stage ch1
    stage(0);
    asm volatile("cp.async.wait_group 0;");
    __syncthreads();
    buildB();
    __syncthreads();
    if (NCHB > 1) stage(1);

    // ldmatrix lane bases
    const int amat = lid >> 3, arow = lid & 7;
    const uint32_t aH = sbase + SM_ABH
        + (uint32_t)(((amat & 1) * 8 + arow) * APITCH + ((amat >> 1) * 8) * 2);
    const uint32_t bbase = sbase + SM_B
        + (uint32_t)((lid & 7) * BPITCH + ((lid >> 3) & 1) * 16);

    // epilogue geometry: thread covers l = 128*tn + tm .. +15
    const int tn = tid >> 3, tm = 16 * (tid & 7);
    const int lt = 128 * tn + tm;
    float* epi = (float*)(sm + SM_EPI);

    #pragma unroll 1
    for (int i = 0; i < NCHB; i++) {
        const long rowc = ((long)b * D_ + g + 256 * (4 * chunk + i)) * L_;

        // q prefetch (LDG latency hidden under the MMA loop)
        float4 qv[4];
        #pragma unroll
        for (int j = 0; j < 4; j++)
            qv[j] = *(const float4*)(q + rowc + lt + 4 * j);

        // -- MMA mainloop; warp w covers banded ksteps w..w+8
        float d[4][4];
        #pragma unroll
        for (int nc = 0; nc < 4; nc++)
            #pragma unroll
            for (int jj = 0; jj < 4; jj++) d[nc][jj] = 0.f;

        #pragma unroll 1
        for (int c = 0; c < 9; c++) {
            uint32_t ah[4], al[4];
            ldsm4(ah, aH + (uint32_t)(32 * c));
            ldsm4(al, aH + (uint32_t)(SM_ABL - SM_ABH + 32 * c));
            const uint32_t koff = 32u * (uint32_t)(wid + c);
            #pragma unroll
            for (int nc = 0; nc < 4; nc++) {
                const uint32_t baddr = bbase + (uint32_t)(nc * 8 * BPITCH) + koff;
                uint32_t bh[2], bl[2];
                ldsm2(bh, baddr);
                ldsm2(bl, baddr + BLO);
                mma16816(d[nc], ah, bh);
                mma16816(d[nc], ah, bl);
                mma16816(d[nc], al, bh);
            }
        }

        // -- D frags -> epi (conflict-free via 132-float pitch)
        {
            const int m = 16 * wid + (lid >> 2);
            #pragma unroll
            for (int nc = 0; nc < 4; nc++) {
                const int n = 8 * nc + 2 * (lid & 3);
                epi[n * EPI_PITCH + m]           = d[nc][0];
                epi[(n + 1) * EPI_PITCH + m]     = d[nc][1];
                epi[n * EPI_PITCH + m + 8]       = d[nc][2];
                epi[(n + 1) * EPI_PITCH + m + 8] = d[nc][3];
            }
        }
        __syncthreads();

        // -- epilogue: q-gated coalesced stores
        {
            float4* op = (float4*)(out + rowc + lt);
            const float4* ep = (const float4*)(epi + tn * EPI_PITCH + tm);
            #pragma unroll
            for (int jj = 0; jj < 4; jj++) {
                float4 y = ep[jj];
                op[jj] = make_float4(qv[jj].x * y.x, qv[jj].y * y.y,
                                     qv[jj].z * y.z, qv[jj].w * y.w);
            }
        }

        // -- consume staged ch i+1 into B; kick stage ch i+2
        if (i + 1 < NCHB) {
            asm volatile("cp.async.wait_group 0;");
            __syncthreads();   // staging visible; epi reads + B reads done
            buildB();
            __syncthreads();   // B visible; staging free
            if (i + 2 < NCHB) stage(i + 2);
        }
    }
}

extern "C" void kernel_launch(void* const* d_in, const int* in_sizes, int n_in,
                              void* d_out, int out_size) {
    // metadata order: x, k, q, h  (all float32); output float32 (B,D,L)
    const float* x = (const float*)d_in[0];
    const float* k = (const float*)d_in[1];
    const float* q = (const float*)d_in[2];
    const float* h = (const float*)d_in[3];
    float* out = (float*)d_out;

    cudaFuncSetAttribute(hyena_mma_kernel,
                         cudaFuncAttributeMaxDynamicSharedMemorySize, SM_TOTAL);
    dim3 grid(G_, B_ * 4);   // 256 groups x (2 batches x 4 channel-chunks)
    hyena_mma_kernel<<<grid, THREADS, SM_TOTAL>>>(x, k, q, h, out);
}

// round 13
// speedup vs baseline: 1.7481x; 1.1564x over previous
#include <cuda_runtime.h>
#include <cuda_bf16.h>
#include <cstdint>

// HyenaSE gated causal depthwise conv via banded-Toeplitz GEMM on
// mma.sync.m16n8k16 (bf16 base ISA; tcgen05 unsupported at sm_103 target).
// y[b,d,l] = q * sum_s (k*x)[b,d,l-s] * h[d%256][127-s]
//
// R13: R12 was occupancy/latency-limited (occ 24%, issue 23%, dur ==
// traffic/BW). Changes:
//  - Epilogue smem transpose DELETED: D fragments stored directly with
//    scattered STG.32 (4 full 32B sectors per instr), q gate loaded the
//    same way. Removes 17KB smem + 2 syncs + smem round-trip.
//  - Half-channel tiles (L split in 2): B = 16 rows, staging = 2176
//    floats/array with the causal halo zero-filled at stage time (no
//    zero-branch in buildB). Smem 43KB -> 4 blocks/SM = 32 warps (2x R12).
// Core: 16x144 Toeplitz band (hi+lo bf16) shared by all warps; warp w
// covers banded ksteps w..w+8; 3-pass Markidis split (rel_err ~4e-6);
// cp.async staging of next half-channel during current MMA.

typedef unsigned long long u64;

#define B_  2
#define D_  4096
#define L_  4096
#define G_  256
#define HL_ 128

static constexpr int THREADS = 256;
static constexpr int NIT = 4;                 // half-channels per block

static constexpr int APITCH = 304;            // Aband row pitch bytes
static constexpr int BPITCH = 528;            // B row pitch bytes
static constexpr int NSTG = 2176;             // staged floats per array

// smem byte offsets
static constexpr int SM_ABH   = 0;            // 16*304 = 4864
static constexpr int SM_ABL   = 4864;         // end 9728
static constexpr int SM_STG_X = 9728;         // 2176*4 = 8704 -> end 18432
static constexpr int SM_STG_K = 18432;        // end 27136
static constexpr int SM_B     = 27136;        // Bh 16*528=8448 + Bl 8448
static constexpr int BLO      = 8448;
static constexpr int SM_TOTAL = 44032;        // 43KB -> 4 blocks/SM

__device__ __forceinline__ void ldsm4(uint32_t* r, uint32_t addr) {
    asm volatile("ldmatrix.sync.aligned.m8n8.x4.shared.b16 {%0,%1,%2,%3}, [%4];"
        : "=r"(r[0]), "=r"(r[1]), "=r"(r[2]), "=r"(r[3]) : "r"(addr));
}
__device__ __forceinline__ void ldsm2(uint32_t* r, uint32_t addr) {
    asm volatile("ldmatrix.sync.aligned.m8n8.x2.shared.b16 {%0,%1}, [%2];"
        : "=r"(r[0]), "=r"(r[1]) : "r"(addr));
}
__device__ __forceinline__ void mma16816(float* d, const uint32_t* a, const uint32_t* b) {
    asm volatile("mma.sync.aligned.m16n8k16.row.col.f32.bf16.bf16.f32 "
        "{%0,%1,%2,%3}, {%4,%5,%6,%7}, {%8,%9}, {%0,%1,%2,%3};"
        : "+f"(d[0]), "+f"(d[1]), "+f"(d[2]), "+f"(d[3])
        : "r"(a[0]), "r"(a[1]), "r"(a[2]), "r"(a[3]), "r"(b[0]), "r"(b[1]));
}
__device__ __forceinline__ void cp16(uint32_t daddr, const void* g) {
    asm volatile("cp.async.cg.shared.global [%0], [%1], 16;"
                 :: "r"(daddr), "l"(g));
}

__device__ __forceinline__ uint32_t pack_hi(float a, float b, float& ra, float& rb) {
    __nv_bfloat16 ha = __float2bfloat16(a), hb = __float2bfloat16(b);
    ra = a - __bfloat162float(ha);
    rb = b - __bfloat162float(hb);
    return (uint32_t)__bfloat16_as_ushort(ha) | ((uint32_t)__bfloat16_as_ushort(hb) << 16);
}
__device__ __forceinline__ uint32_t pack_lo(float ra, float rb) {
    __nv_bfloat16 la = __float2bfloat16(ra), lb = __float2bfloat16(rb);
    return (uint32_t)__bfloat16_as_ushort(la) | ((uint32_t)__bfloat16_as_ushort(lb) << 16);
}

__global__ void __launch_bounds__(THREADS, 4)
hyena_mma_kernel(const float* __restrict__ x, const float* __restrict__ k,
                 const float* __restrict__ q, const float* __restrict__ h,
                 float* __restrict__ out)
{
    extern __shared__ __align__(16) char sm[];
    const uint32_t sbase = (uint32_t)__cvta_generic_to_shared(sm);
    const int tid = threadIdx.x, wid = tid >> 5, lid = tid & 31;
    const int g = blockIdx.x;
    const int half  = blockIdx.y & 1;
    const int b     = (blockIdx.y >> 1) & 1;
    const int chunk = blockIdx.y >> 2;           // 0..3: channels 4*chunk+i

    // ---- Toeplitz band: Aband[r][u] = h[g][u-r-1], u in [0,144), hi+lo
    {
        const float* hg = h + g * HL_;
        const int r = tid & 15;
        const int u0 = (tid >> 4) * 9;
        __nv_bfloat16* abh = (__nv_bfloat16*)(sm + SM_ABH + r * APITCH);
        __nv_bfloat16* abl = (__nv_bfloat16*)(sm + SM_ABL + r * APITCH);
        #pragma unroll
        for (int i = 0; i < 9; i++) {
            const int u = u0 + i;
            const int s = u - r - 1;
            float v = (s >= 0 && s < HL_) ? hg[s] : 0.f;
            __nv_bfloat16 vh = __float2bfloat16(v);
            abh[u] = vh;
            abl[u] = __float2bfloat16(v - __bfloat162float(vh));
        }
    }

    // Row base of channel (4*chunk+i); outputs live at +2048*half.
    auto chanRow = [&](int i) -> long {
        return ((long)b * D_ + g + 256 * (4 * chunk + i)) * L_;
    };

    // Stage xs/ks = raw floats at [chanRow + 2048*half - 128, +2176).
    // For half==0 the first 128 floats are causal zeros (filled here).
    auto stage = [&](int i) {
        const long base = chanRow(i) + 2048 * half - 128;
        #pragma unroll
        for (int v = tid; v < 2 * (NSTG / 4); v += THREADS) {  // 272 float4
            const int isK = (v >= NSTG / 4);
            const int vv  = isK ? v - NSTG / 4 : v;
            const uint32_t daddr = sbase + (isK ? SM_STG_K : SM_STG_X)
                                 + (uint32_t)vv * 16;
            if (half == 0 && vv < 32) {
                *(float4*)(sm + (isK ? SM_STG_K : SM_STG_X) + vv * 16)
                    = make_float4(0.f, 0.f, 0.f, 0.f);
            } else {
                const float* src = (isK ? k : x) + base + 4 * (long)vv;
                cp16(daddr, src);
            }
        }
        asm volatile("cp.async.commit_group;");
    };

    // Build B[n][j] = xs[128n+j]*ks[128n+j] (n<16, j<256), bf16 hi+lo.
    const int bn = tid >> 4;           // 0..15
    const int bj = 4 * (tid & 15);     // 0..60
    auto buildB = [&]() {
        const float* xs = (const float*)(sm + SM_STG_X);
        const float* ks = (const float*)(sm + SM_STG_K);
        #pragma unroll
        for (int c = 0; c < 4; c++) {
            const int pos = 128 * bn + bj + 64 * c;
            float4 xv = *(const float4*)(xs + pos);
            float4 kv = *(const float4*)(ks + pos);
            float r0, r1, r2, r3;
            uint32_t h01 = pack_hi(xv.x * kv.x, xv.y * kv.y, r0, r1);
            uint32_t h23 = pack_hi(xv.z * kv.z, xv.w * kv.w, r2, r3);
            uint32_t l01 = pack_lo(r0, r1);
            uint32_t l23 = pack_lo(r2, r3);
            const uint32_t off = (uint32_t)bn * BPITCH
                               + (uint32_t)(bj + 64 * c) * 2;
            *(uint2*)(sm + SM_B + off)       = make_uint2(h01, h23);
            *(uint2*)(sm + SM_B + BLO + off) = make_uint2(l01, l23);
        }
    };

    // ---- prologue
    stage(0);
    asm volatile("cp.async.wait_group 0;");
    __syncthreads();                   // staging + Aband visible
    buildB();
    __syncthreads();                   // B visible; staging free
    stage(1);

    // ldmatrix lane bases
    const int amat = lid >> 3, arow = lid & 7;
    const uint32_t aH = sbase + SM_ABH
        + (uint32_t)(((amat & 1) * 8 + arow) * APITCH + ((amat >> 1) * 8) * 2);
    const uint32_t bbase = sbase + SM_B
        + (uint32_t)((lid & 7) * BPITCH + ((lid >> 3) & 1) * 16);

    // Fragment-direct output geometry
    const int m0 = 16 * wid + (lid >> 2);
    const int n0 = 2 * (lid & 3);

    #pragma unroll 1
    for (int i = 0; i < NIT; i++) {
        // -- MMA mainloop; warp w covers banded ksteps w..w+8
        float d[2][4];
        #pragma unroll
        for (int nc = 0; nc < 2; nc++)
            #pragma unroll
            for (int jj = 0; jj < 4; jj++) d[nc][jj] = 0.f;

        #pragma unroll 1
        for (int c = 0; c < 9; c++) {
            uint32_t ah[4], al[4];
            ldsm4(ah, aH + (uint32_t)(32 * c));
            ldsm4(al, aH + (uint32_t)(SM_ABL - SM_ABH + 32 * c));
            const uint32_t koff = 32u * (uint32_t)(wid + c);
            #pragma unroll
            for (int nc = 0; nc < 2; nc++) {
                const uint32_t baddr = bbase + (uint32_t)(nc * 8 * BPITCH) + koff;
                uint32_t bh[2], bl[2];
                ldsm2(bh, baddr);
                ldsm2(bl, baddr + BLO);
                mma16816(d[nc], ah, bh);
                mma16816(d[nc], ah, bl);
                mma16816(d[nc], al, bh);
            }
        }

        // -- direct scattered q-gate + store: l = 2048*half + 128n + m
        {
            const long rowc = chanRow(i) + 2048 * half;
            float qv[8];
            #pragma unroll
            for (int nc = 0; nc < 2; nc++)
                #pragma unroll
                for (int jj = 0; jj < 4; jj++) {
                    const int n = 8 * nc + n0 + (jj & 1);
                    const int m = m0 + 8 * (jj >> 1);
                    qv[nc * 4 + jj] = q[rowc + 128 * n + m];
                }
            #pragma unroll
            for (int nc = 0; nc < 2; nc++)
                #pragma unroll
                for (int jj = 0; jj < 4; jj++) {
                    const int n = 8 * nc + n0 + (jj & 1);
                    const int m = m0 + 8 * (jj >> 1);
                    out[rowc + 128 * n + m] = qv[nc * 4 + jj] * d[nc][jj];
                }
        }

        // -- consume staged half-channel i+1; kick stage i+2
        if (i + 1 < NIT) {
            asm volatile("cp.async.wait_group 0;");
            __syncthreads();           // staging visible; B reads done
            buildB();
            __syncthreads();           // B visible; staging free
            if (i + 2 < NIT) stage(i + 2);
        }
    }
}

extern "C" void kernel_launch(void* const* d_in, const int* in_sizes, int n_in,
                              void* d_out, int out_size) {
    // metadata order: x, k, q, h  (all float32); output float32 (B,D,L)
    const float* x = (const float*)d_in[0];
    const float* k = (const float*)d_in[1];
    const float* q = (const float*)d_in[2];
    const float* h = (const float*)d_in[3];
    float* out = (float*)d_out;

    cudaFuncSetAttribute(hyena_mma_kernel,
                         cudaFuncAttributeMaxDynamicSharedMemorySize, SM_TOTAL);
    // grid.y: bit0 = L-half, bit1 = batch, bits2+ = 4-channel chunk
    dim3 grid(G_, B_ * 2 * 4);   // 256 x 16 = 4096 blocks
    hyena_mma_kernel<<<grid, THREADS, SM_TOTAL>>>(x, k, q, h, out);
}

// round 14
// speedup vs baseline: 2.0634x; 1.1804x over previous
#include <cuda_runtime.h>
#include <cuda_fp16.h>
#include <cstdint>

// HyenaSE gated causal depthwise conv via banded-Toeplitz GEMM on
// mma.sync.m16n8k16 (fp16, base ISA; tcgen05 unsupported at sm_103 target).
// y[b,d,l] = q * sum_s (k*x)[b,d,l-s] * h[d%256][127-s]
//
// R14: R13 was L1-wavefront-bound (L1=90.6%; wf audit matches dur). Cut
// bytes: fp16 (10-bit mantissa) 2-term split. A = Toeplitz band split
// exactly (Ah+Al); B rounded once to fp16. Error = A*(B-Bh) ~ 2^-12
// random-walk => rel_err ~2-4e-4 < 1e-3. Drops Bl (buildB + B smem
// halve) and the 3rd MMA pass. Smem 35KB -> 5 blocks/SM (occ 62.5%).
// Else as R13: 16x144 band shared by all warps, banded ksteps w..w+8,
// cp.async staging of next half-channel under current MMA, direct
// scattered fragment epilogue (4 full 32B sectors per STG.32).

typedef unsigned long long u64;

#define B_  2
#define D_  4096
#define L_  4096
#define G_  256
#define HL_ 128

static constexpr int THREADS = 256;
static constexpr int NIT = 4;                 // half-channels per block

static constexpr int APITCH = 304;            // Aband row pitch bytes
static constexpr int BPITCH = 528;            // B row pitch bytes
static constexpr int NSTG = 2176;             // staged floats per array

// smem byte offsets
static constexpr int SM_ABH   = 0;            // 16*304 = 4864
static constexpr int SM_ABL   = 4864;         // end 9728
static constexpr int SM_STG_X = 9728;         // 2176*4 = 8704 -> 18432
static constexpr int SM_STG_K = 18432;        // -> 27136
static constexpr int SM_B     = 27136;        // Bh only: 16*528 = 8448
static constexpr int SM_TOTAL = 35584;        // ~35KB -> 5 blocks/SM

__device__ __forceinline__ void ldsm4(uint32_t* r, uint32_t addr) {
    asm volatile("ldmatrix.sync.aligned.m8n8.x4.shared.b16 {%0,%1,%2,%3}, [%4];"
        : "=r"(r[0]), "=r"(r[1]), "=r"(r[2]), "=r"(r[3]) : "r"(addr));
}
__device__ __forceinline__ void ldsm2(uint32_t* r, uint32_t addr) {
    asm volatile("ldmatrix.sync.aligned.m8n8.x2.shared.b16 {%0,%1}, [%2];"
        : "=r"(r[0]), "=r"(r[1]) : "r"(addr));
}
__device__ __forceinline__ void mma16816(float* d, const uint32_t* a, const uint32_t* b) {
    asm volatile("mma.sync.aligned.m16n8k16.row.col.f32.f16.f16.f32 "
        "{%0,%1,%2,%3}, {%4,%5,%6,%7}, {%8,%9}, {%0,%1,%2,%3};"
        : "+f"(d[0]), "+f"(d[1]), "+f"(d[2]), "+f"(d[3])
        : "r"(a[0]), "r"(a[1]), "r"(a[2]), "r"(a[3]), "r"(b[0]), "r"(b[1]));
}
__device__ __forceinline__ void cp16(uint32_t daddr, const void* g) {
    asm volatile("cp.async.cg.shared.global [%0], [%1], 16;"
                 :: "r"(daddr), "l"(g));
}
__device__ __forceinline__ uint32_t pack_h2(float a, float b) {
    __half2 p = __floats2half2_rn(a, b);
    return *(uint32_t*)&p;
}

__global__ void __launch_bounds__(THREADS, 5)
hyena_mma_kernel(const float* __restrict__ x, const float* __restrict__ k,
                 const float* __restrict__ q, const float* __restrict__ h,
                 float* __restrict__ out)
{
    extern __shared__ __align__(16) char sm[];
    const uint32_t sbase = (uint32_t)__cvta_generic_to_shared(sm);
    const int tid = threadIdx.x, wid = tid >> 5, lid = tid & 31;
    const int g = blockIdx.x;
    const int half  = blockIdx.y & 1;
    const int b     = (blockIdx.y >> 1) & 1;
    const int chunk = blockIdx.y >> 2;           // 0..3: channels 4*chunk+i

    // ---- Toeplitz band: Aband[r][u] = h[g][u-r-1], u in [0,144).
    // Exact fp16 split: A = Ah + Al (Al = fp16(A - float(Ah))).
    {
        const float* hg = h + g * HL_;
        const int r = tid & 15;
        const int u0 = (tid >> 4) * 9;
        __half* abh = (__half*)(sm + SM_ABH + r * APITCH);
        __half* abl = (__half*)(sm + SM_ABL + r * APITCH);
        #pragma unroll
        for (int i = 0; i < 9; i++) {
            const int u = u0 + i;
            const int s = u - r - 1;
            float v = (s >= 0 && s < HL_) ? hg[s] : 0.f;
            __half vh = __float2half_rn(v);
            abh[u] = vh;
            abl[u] = __float2half_rn(v - __half2float(vh));
        }
    }

    auto chanRow = [&](int i) -> long {
        return ((long)b * D_ + g + 256 * (4 * chunk + i)) * L_;
    };

    // Stage xs/ks = raw floats at [chanRow + 2048*half - 128, +2176).
    // half==0: first 128 floats are causal zeros.
    auto stage = [&](int i) {
        const long base = chanRow(i) + 2048 * half - 128;
        #pragma unroll
        for (int v = tid; v < 2 * (NSTG / 4); v += THREADS) {  // 272 float4
            const int isK = (v >= NSTG / 4);
            const int vv  = isK ? v - NSTG / 4 : v;
            const uint32_t daddr = sbase + (isK ? SM_STG_K : SM_STG_X)
                                 + (uint32_t)vv * 16;
            if (half == 0 && vv < 32) {
                *(float4*)(sm + (isK ? SM_STG_K : SM_STG_X) + vv * 16)
                    = make_float4(0.f, 0.f, 0.f, 0.f);
            } else {
                const float* src = (isK ? k : x) + base + 4 * (long)vv;
                cp16(daddr, src);
            }
        }
        asm volatile("cp.async.commit_group;");
    };

    // Build Bh[n][j] = fp16(xs[128n+j]*ks[128n+j]) (n<16, j<256).
    const int bn = tid >> 4;           // 0..15
    const int bj = 4 * (tid & 15);     // 0..60
    auto buildB = [&]() {
        const float* xs = (const float*)(sm + SM_STG_X);
        const float* ks = (const float*)(sm + SM_STG_K);
        #pragma unroll
        for (int c = 0; c < 4; c++) {
            const int pos = 128 * bn + bj + 64 * c;
            float4 xv = *(const float4*)(xs + pos);
            float4 kv = *(const float4*)(ks + pos);
            uint2 pk = make_uint2(pack_h2(xv.x * kv.x, xv.y * kv.y),
                                  pack_h2(xv.z * kv.z, xv.w * kv.w));
            *(uint2*)(sm + SM_B + (uint32_t)bn * BPITCH
                      + (uint32_t)(bj + 64 * c) * 2) = pk;
        }
    };

    // ---- prologue
    stage(0);
    asm volatile("cp.async.wait_group 0;");
    __syncthreads();                   // staging + Aband visible
    buildB();
    __syncthreads();                   // B visible; staging free
    stage(1);

    // ldmatrix lane bases
    const int amat = lid >> 3, arow = lid & 7;
    const uint32_t aH = sbase + SM_ABH
        + (uint32_t)(((amat & 1) * 8 + arow) * APITCH + ((amat >> 1) * 8) * 2);
    const uint32_t bbase = sbase + SM_B
        + (uint32_t)((lid & 7) * BPITCH + ((lid >> 3) & 1) * 16);

    // Fragment-direct output geometry
    const int m0 = 16 * wid + (lid >> 2);
    const int n0 = 2 * (lid & 3);

    #pragma unroll 1
    for (int i = 0; i < NIT; i++) {
        // -- MMA mainloop; warp w covers banded ksteps w..w+8
        float d[2][4];
        #pragma unroll
        for (int nc = 0; nc < 2; nc++)
            #pragma unroll
            for (int jj = 0; jj < 4; jj++) d[nc][jj] = 0.f;

        #pragma unroll 1
        for (int c = 0; c < 9; c++) {
            uint32_t ah[4], al[4];
            ldsm4(ah, aH + (uint32_t)(32 * c));
            ldsm4(al, aH + (uint32_t)(SM_ABL - SM_ABH + 32 * c));
            const uint32_t koff = 32u * (uint32_t)(wid + c);
            #pragma unroll
            for (int nc = 0; nc < 2; nc++) {
                uint32_t bh[2];
                ldsm2(bh, bbase + (uint32_t)(nc * 8 * BPITCH) + koff);
                mma16816(d[nc], ah, bh);
                mma16816(d[nc], al, bh);
            }
        }

        // -- direct scattered q-gate + store: l = 2048*half + 128n + m
        {
            const long rowc = chanRow(i) + 2048 * half;
            float qv[8];
            #pragma unroll
            for (int nc = 0; nc < 2; nc++)
                #pragma unroll
                for (int jj = 0; jj < 4; jj++) {
                    const int n = 8 * nc + n0 + (jj & 1);
                    const int m = m0 + 8 * (jj >> 1);
                    qv[nc * 4 + jj] = q[rowc + 128 * n + m];
                }
            #pragma unroll
            for (int nc = 0; nc < 2; nc++)
                #pragma unroll
                for (int jj = 0; jj < 4; jj++) {
                    const int n = 8 * nc + n0 + (jj & 1);
                    const int m = m0 + 8 * (jj >> 1);
                    out[rowc + 128 * n + m] = qv[nc * 4 + jj] * d[nc][jj];
                }
        }

        // -- consume staged half-channel i+1; kick stage i+2
        if (i + 1 < NIT) {
            asm volatile("cp.async.wait_group 0;");
            __syncthreads();           // staging visible; B reads done
            buildB();
            __syncthreads();           // B visible; staging free
            if (i + 2 < NIT) stage(i + 2);
        }
    }
}

extern "C" void kernel_launch(void* const* d_in, const int* in_sizes, int n_in,
                              void* d_out, int out_size) {
    // metadata order: x, k, q, h  (all float32); output float32 (B,D,L)
    const float* x = (const float*)d_in[0];
    const float* k = (const float*)d_in[1];
    const float* q = (const float*)d_in[2];
    const float* h = (const float*)d_in[3];
    float* out = (float*)d_out;

    cudaFuncSetAttribute(hyena_mma_kernel,
                         cudaFuncAttributeMaxDynamicSharedMemorySize, SM_TOTAL);
    // grid.y: bit0 = L-half, bit1 = batch, bits2+ = 4-channel chunk
    dim3 grid(G_, B_ * 2 * 4);   // 256 x 16 = 4096 blocks
    hyena_mma_kernel<<<grid, THREADS, SM_TOTAL>>>(x, k, q, h, out);
}